// round 17
// baseline (speedup 1.0000x reference)
#include <cuda_runtime.h>
#include <cuda_fp16.h>
#include <cstdint>

// ---------------- problem constants ----------------
#define NPOS   8000
#define CCH    128
#define CQ     16
#define NSPLIT 2         // splits of 63 / 62 j-tiles -> grid 250 = ONE wave
#define QT     125       // q tiles of 64

#define QKPITCH 24       // Q/K smem pitch (halfs) -> 48B rows, ldsm conflict-free
#define VPITCH  72       // V smem pitch (halfs) -> 144B rows, conflict-free
#define PPITCH  72       // P smem pitch (halfs)

// smem byte offsets (4 K/V buffers = 2 pairs, double-buffered P)
#define OFF_Q  0                    // half [64][24]           3072 B
#define KBUF   3072
#define OFF_K  3072                 // half [4][64][24]       12288 B
#define VBUF   18432
#define OFF_V  15360                // half [4][128][72]      73728 B
#define PBUF   9216
#define OFF_P  89088                // half [2][64][72]       18432 B
#define OFF_L  107520               // float [64]               256 B
#define FLASH_SMEM 107776

// ---------------- device scratch ----------------
__device__ __half g_q[NPOS * CQ];            // [n][d], fp16
__device__ __half g_k[NPOS * CQ];            // [n][d], fp16
__device__ __half g_v[(size_t)CCH * NPOS];   // [c][n], fp16
__device__ float  g_waT[CCH * CCH];
__device__ float  g_pacc[(size_t)NSPLIT * NPOS * CCH];
__device__ float  g_pl[NSPLIT * NPOS];
__device__ float  g_y[(size_t)CCH * NPOS];
__device__ float  g_sum[CCH], g_sq[CCH];

// ---------------- helpers ----------------
__device__ __forceinline__ uint32_t smem_u32(const void* p) {
    uint32_t a;
    asm("{ .reg .u64 t; cvta.to.shared.u64 t, %1; cvt.u32.u64 %0, t; }" : "=r"(a) : "l"(p));
    return a;
}
__device__ __forceinline__ void mma_f16(float d[4],
                                        uint32_t a0, uint32_t a1, uint32_t a2, uint32_t a3,
                                        uint32_t b0, uint32_t b1) {
    asm volatile("mma.sync.aligned.m16n8k16.row.col.f32.f16.f16.f32 "
                 "{%0,%1,%2,%3}, {%4,%5,%6,%7}, {%8,%9}, {%0,%1,%2,%3};"
                 : "+f"(d[0]), "+f"(d[1]), "+f"(d[2]), "+f"(d[3])
                 : "r"(a0), "r"(a1), "r"(a2), "r"(a3), "r"(b0), "r"(b1));
}
__device__ __forceinline__ void ldsm4(uint32_t r[4], uint32_t addr) {
    asm volatile("ldmatrix.sync.aligned.m8n8.x4.shared.b16 {%0,%1,%2,%3}, [%4];"
                 : "=r"(r[0]), "=r"(r[1]), "=r"(r[2]), "=r"(r[3]) : "r"(addr));
}
#define CPA16(dst, src) \
    asm volatile("cp.async.cg.shared.global [%0], [%1], 16;" :: "r"(dst), "l"(src))
#define CP_COMMIT() asm volatile("cp.async.commit_group;" ::: "memory")
#define CP_WAIT0()  asm volatile("cp.async.wait_group 0;" ::: "memory")

// ---------------- kernel: fused preprocessing ----------------
// blocks 0..63: transpose wa (+zero stats); 64..313: q/k proj; 314..813: v proj
__global__ void __launch_bounds__(256) k_pre(const float* __restrict__ x,
                                             const float* __restrict__ wq,
                                             const float* __restrict__ bq,
                                             const float* __restrict__ wk,
                                             const float* __restrict__ bk,
                                             const float* __restrict__ wv,
                                             const float* __restrict__ bv,
                                             const float* __restrict__ wa) {
    __shared__ float swT[CCH * 32];   // 16 KB, reused by both proj paths
    __shared__ float sb[32];
    const int b = blockIdx.x;
    const int tid = threadIdx.x;

    if (b < 64) {
        int i = b * 256 + tid;
        if (i < CCH) { g_sum[i] = 0.f; g_sq[i] = 0.f; }
        int r = i >> 7, c = i & 127;
        g_waT[c * CCH + r] = wa[r * CCH + c];
        return;
    }

    if (b < 314) {
        // ---- q/k projection ----
        for (int i = tid; i < 16 * CCH; i += 256) {
            int d = i >> 7, cc = i & 127;
            swT[cc * 32 + d]      = wq[i];
            swT[cc * 32 + 16 + d] = wk[i];
        }
        if (tid < 16) sb[tid] = bq[tid];
        else if (tid < 32) sb[tid] = bk[tid - 16];
        __syncthreads();

        const int n  = (b - 64) * 32 + (tid & 31);
        const int og = tid >> 5;
        float a0 = sb[og * 4 + 0], a1 = sb[og * 4 + 1];
        float a2 = sb[og * 4 + 2], a3 = sb[og * 4 + 3];
        #pragma unroll 4
        for (int cc = 0; cc < CCH; cc++) {
            float xv = x[cc * NPOS + n];
            float4 w = *(const float4*)&swT[cc * 32 + og * 4];
            a0 += w.x * xv; a1 += w.y * xv; a2 += w.z * xv; a3 += w.w * xv;
        }
        __half* o = (og < 4) ? g_q : g_k;
        int d0 = (og < 4) ? og * 4 : (og - 4) * 4;
        o[n * CQ + d0 + 0] = __float2half_rn(a0);
        o[n * CQ + d0 + 1] = __float2half_rn(a1);
        o[n * CQ + d0 + 2] = __float2half_rn(a2);
        o[n * CQ + d0 + 3] = __float2half_rn(a3);
        return;
    }

    // ---- v projection ----
    {
        const int vb = b - 314;                 // 0..499
        const int nb = (vb % 125) * 64;
        const int cb = (vb / 125) * 32;
        for (int i = tid; i < 32 * CCH; i += 256) {
            int r = i >> 7, c = i & 127;
            swT[i] = wv[(cb + r) * CCH + c];
        }
        __syncthreads();
        const int n = nb + (tid & 63);
        const int c0 = (tid >> 6) * 8;
        float acc[8];
        #pragma unroll
        for (int i = 0; i < 8; i++) acc[i] = bv[cb + c0 + i];
        #pragma unroll 4
        for (int cc4 = 0; cc4 < 32; cc4++) {
            float x0 = x[(cc4 * 4 + 0) * NPOS + n];
            float x1 = x[(cc4 * 4 + 1) * NPOS + n];
            float x2 = x[(cc4 * 4 + 2) * NPOS + n];
            float x3 = x[(cc4 * 4 + 3) * NPOS + n];
            #pragma unroll
            for (int i = 0; i < 8; i++) {
                float4 w = *(const float4*)&swT[(c0 + i) * CCH + cc4 * 4];
                acc[i] += w.x * x0 + w.y * x1 + w.z * x2 + w.w * x3;
            }
        }
        #pragma unroll
        for (int i = 0; i < 8; i++)
            g_v[(size_t)(cb + c0 + i) * NPOS + n] = __float2half_rn(acc[i]);
    }
}

// ---------------- kernel: flash attention, 2 tiles per barrier window ----------------
__global__ void __launch_bounds__(256, 2) k_flash_mma() {
    extern __shared__ char smc[];
    float* sL = (float*)(smc + OFF_L);
    const uint32_t smb = smem_u32(smc);

    const int tid  = threadIdx.x;
    const int wid  = tid >> 5;
    const int lane = tid & 31;
    const int g    = lane >> 2;     // groupID (0..7)
    const int tq   = lane & 3;      // threadID_in_group

    const int qt = blockIdx.x, sp = blockIdx.y;
    const int qbase = qt * 64;
    const int jt0   = sp ? 63 : 0;
    const int niter = sp ? 62 : 63;

    // MMA1/softmax mapping: 4 q-blocks x 2 j-halves
    const int qb = (wid >> 1) * 16;
    const int jh = (wid & 1) * 32;
    // MMA2 mapping: 2 q-halves x 4 c-quarters
    const int qh2 = (wid >> 2) * 32;
    const int cq  = (wid & 3) * 32;

    if (tid < 64) sL[tid] = 0.f;

    // load Q tile: 64 rows x 16 halfs
    if (tid < 128) {
        int row = tid >> 1, seg = tid & 1;
        *(uint4*)(smc + OFF_Q + row * (QKPITCH * 2) + seg * 16) =
            *(const uint4*)&g_q[(qbase + row) * CQ + seg * 8];
    }

    // prefetch pointers
    const int krow = tid >> 1, kseg = tid & 1;     // tid<128 only
    const int vc0 = tid >> 3, vj16 = tid & 7;
    const __half* srcK = &g_k[(jt0 * 64 + krow) * CQ + kseg * 8];
    const __half* srcV = &g_v[(size_t)vc0 * NPOS + jt0 * 64 + vj16 * 8];
    const uint32_t dstK0 = smb + OFF_K + (uint32_t)(krow * QKPITCH + kseg * 8) * 2;
    const uint32_t dstV0 = smb + OFF_V + (uint32_t)(vc0 * VPITCH + vj16 * 8) * 2;

    auto prefetch = [&](int bufi) {
        if (tid < 128) CPA16(dstK0 + bufi * KBUF, srcK);
        uint32_t dv = dstV0 + bufi * VBUF;
        #pragma unroll
        for (int i = 0; i < 4; i++)      // 4 x (32 c-rows)
            CPA16(dv + i * (32 * VPITCH * 2), srcV + (size_t)i * 32 * NPOS);
        CP_COMMIT();
        srcK += 64 * CQ;
        srcV += 64;
    };

    float D[2][4][4];
    #pragma unroll
    for (int qi = 0; qi < 2; qi++)
        #pragma unroll
        for (int nt = 0; nt < 4; nt++)
            #pragma unroll
            for (int k = 0; k < 4; k++) D[qi][nt][k] = 0.f;
    float l0 = 0.f, l1 = 0.f;

    prefetch(0);       // tile 0 -> buffer 0
    prefetch(1);       // tile 1 -> buffer 1  (niter >= 2 always)
    __syncthreads();   // Q visible before hoisted ldmatrix

    // hoisted Q A-fragment (loop-invariant)
    uint32_t qa[4];
    ldsm4(qa, smb + OFF_Q + (uint32_t)((qb + (lane & 15)) * QKPITCH + (lane >> 4) * 8) * 2);

    // ldsm per-thread byte offsets
    const uint32_t bK = (uint32_t)(((lane & 7) + ((lane >> 4) * 8)) * QKPITCH
                                   + ((lane >> 3) & 1) * 8) * 2;
    const uint32_t aoff = (uint32_t)((lane & 15) * PPITCH + (lane >> 4) * 8) * 2;
    const uint32_t boff = (uint32_t)(((lane & 7) + ((lane >> 4) * 8)) * VPITCH
                                     + ((lane >> 3) & 1) * 8) * 2;

    // process one tile from K/V buffer bufi, using P buffer pb
    auto process = [&](int bufi, int pb) {
        // ---- MMA1 (fp16 k16): S[16q x 32j] per warp ----
        float S[4][4];
        #pragma unroll
        for (int nt = 0; nt < 4; nt++)
            #pragma unroll
            for (int k = 0; k < 4; k++) S[nt][k] = 0.f;
        {
            const uint32_t kbase = smb + OFF_K + bufi * KBUF;
            uint32_t kb0[4], kb1[4];
            ldsm4(kb0, kbase + (uint32_t)(jh * QKPITCH) * 2 + bK);
            ldsm4(kb1, kbase + (uint32_t)((jh + 16) * QKPITCH) * 2 + bK);
            mma_f16(S[0], qa[0], qa[1], qa[2], qa[3], kb0[0], kb0[1]);
            mma_f16(S[1], qa[0], qa[1], qa[2], qa[3], kb0[2], kb0[3]);
            mma_f16(S[2], qa[0], qa[1], qa[2], qa[3], kb1[0], kb1[1]);
            mma_f16(S[3], qa[0], qa[1], qa[2], qa[3], kb1[2], kb1[3]);
        }

        // ---- softmax (no max-subtraction) + fp16 pack + store P[pb] ----
        {
            char* pB = smc + OFF_P + pb * PBUF;
            #pragma unroll
            for (int nt = 0; nt < 4; nt++) {
                float p0 = __expf(S[nt][0]);
                float p1 = __expf(S[nt][1]);
                float p2 = __expf(S[nt][2]);
                float p3 = __expf(S[nt][3]);
                l0 += p0 + p1;
                l1 += p2 + p3;
                int col = jh + nt * 8 + 2 * tq;
                *(__half2*)(pB + ((qb + g) * PPITCH + col) * 2) =
                    __floats2half2_rn(p0, p1);
                *(__half2*)(pB + ((qb + g + 8) * PPITCH + col) * 2) =
                    __floats2half2_rn(p2, p3);
            }
        }
        // named split barrier: P rows 0-31 <-> warps 0-3; rows 32-63 <-> warps 4-7
        if (wid < 4) asm volatile("bar.sync 3, 128;" ::: "memory");
        else         asm volatile("bar.sync 4, 128;" ::: "memory");

        // ---- MMA2 (fp16 k16): D[32q x 32c] per warp ----
        {
            const uint32_t pbase = smb + OFF_P + pb * PBUF;
            const uint32_t vbase = smb + OFF_V + bufi * VBUF;
            #pragma unroll
            for (int kc = 0; kc < 4; kc++) {
                uint32_t pa0[4], pa1[4], vb0[4], vb1[4];
                ldsm4(pa0, pbase + (uint32_t)(qh2 * PPITCH) * 2 + kc * 32 + aoff);
                ldsm4(pa1, pbase + (uint32_t)((qh2 + 16) * PPITCH) * 2 + kc * 32 + aoff);
                ldsm4(vb0, vbase + (uint32_t)(cq * VPITCH) * 2 + kc * 32 + boff);
                ldsm4(vb1, vbase + (uint32_t)((cq + 16) * VPITCH) * 2 + kc * 32 + boff);
                mma_f16(D[0][0], pa0[0], pa0[1], pa0[2], pa0[3], vb0[0], vb0[1]);
                mma_f16(D[0][1], pa0[0], pa0[1], pa0[2], pa0[3], vb0[2], vb0[3]);
                mma_f16(D[0][2], pa0[0], pa0[1], pa0[2], pa0[3], vb1[0], vb1[1]);
                mma_f16(D[0][3], pa0[0], pa0[1], pa0[2], pa0[3], vb1[2], vb1[3]);
                mma_f16(D[1][0], pa1[0], pa1[1], pa1[2], pa1[3], vb0[0], vb0[1]);
                mma_f16(D[1][1], pa1[0], pa1[1], pa1[2], pa1[3], vb0[2], vb0[3]);
                mma_f16(D[1][2], pa1[0], pa1[1], pa1[2], pa1[3], vb1[0], vb1[1]);
                mma_f16(D[1][3], pa1[0], pa1[1], pa1[2], pa1[3], vb1[2], vb1[3]);
            }
        }
    };

    const int nwin = niter >> 1;
    const int odd  = niter & 1;
    int pair = 0;
    int pf = 2;   // tiles prefetched so far

    for (int w = 0; w < nwin; w++) {
        CP_WAIT0();
        __syncthreads();   // window barrier: current pair ready; all warps done
                           // with previous window (so prefetch below is WAR-safe)
        int nb = (pair ^ 1) * 2;
        if (pf < niter) { prefetch(nb); pf++; }
        if (pf < niter) { prefetch(nb + 1); pf++; }

        process(pair * 2 + 0, 0);
        process(pair * 2 + 1, 1);
        pair ^= 1;
    }
    if (odd) {
        CP_WAIT0();
        __syncthreads();
        process(pair * 2, 0);
    }

    // ---- l reduction ----
    l0 += __shfl_xor_sync(0xffffffffu, l0, 1);
    l0 += __shfl_xor_sync(0xffffffffu, l0, 2);
    l1 += __shfl_xor_sync(0xffffffffu, l1, 1);
    l1 += __shfl_xor_sync(0xffffffffu, l1, 2);
    if (tq == 0) {
        atomicAdd(&sL[qb + g], l0);
        atomicAdd(&sL[qb + g + 8], l1);
    }
    __syncthreads();
    if (tid < 64)
        g_pl[sp * NPOS + qbase + tid] = sL[tid];

    // ---- write D partials ----
    #pragma unroll
    for (int qi = 0; qi < 2; qi++) {
        #pragma unroll
        for (int nt = 0; nt < 4; nt++) {
            int col = cq + nt * 8 + 2 * tq;
            int r0 = qbase + qh2 + qi * 16 + g;
            *(float2*)&g_pacc[((size_t)sp * NPOS + r0) * CCH + col] =
                make_float2(D[qi][nt][0], D[qi][nt][1]);
            *(float2*)&g_pacc[((size_t)sp * NPOS + r0 + 8) * CCH + col] =
                make_float2(D[qi][nt][2], D[qi][nt][3]);
        }
    }
}

// ---- kernel: fused combine + output projection + BN stat partials ----------
// n-tile = 32 -> grid 250 (fills the chip)
__global__ void __launch_bounds__(256) k_ygemm(const float* __restrict__ ba) {
    __shared__ float avs[32 * CCH];     // 16 KB
    __shared__ float sLr[32];
    __shared__ float ssum[CCH], ssq[CCH];
    const int tid = threadIdx.x;
    const int nbase = blockIdx.x * 32;

    if (tid < 32) {
        float L = 0.f;
        #pragma unroll
        for (int s = 0; s < NSPLIT; s++) L += g_pl[s * NPOS + nbase + tid];
        sLr[tid] = 1.f / L;
    }
    if (tid < CCH) { ssum[tid] = 0.f; ssq[tid] = 0.f; }
    __syncthreads();

    // combine splits directly into the smem tile
    for (int t = tid; t < 32 * (CCH / 4); t += 256) {
        int n = t >> 5;
        int c4 = (t & 31) << 2;
        float4 a = make_float4(0.f, 0.f, 0.f, 0.f);
        #pragma unroll
        for (int s = 0; s < NSPLIT; s++) {
            float4 p = *(const float4*)&g_pacc[((size_t)s * NPOS + nbase + n) * CCH + c4];
            a.x += p.x; a.y += p.y; a.z += p.z; a.w += p.w;
        }
        float r = sLr[n];
        a.x *= r; a.y *= r; a.z *= r; a.w *= r;
        *(float4*)&avs[n * CCH + c4] = a;
    }
    __syncthreads();

    const int c0 = (tid & 31) * 4;
    const int n0 = (tid >> 5) * 4;
    float acc[4][4];
    #pragma unroll
    for (int i = 0; i < 4; i++)
        #pragma unroll
        for (int k = 0; k < 4; k++) acc[i][k] = 0.f;
    #pragma unroll 2
    for (int cc = 0; cc < CCH; cc += 4) {
        float4 w0 = *(const float4*)&g_waT[(cc + 0) * CCH + c0];
        float4 w1 = *(const float4*)&g_waT[(cc + 1) * CCH + c0];
        float4 w2 = *(const float4*)&g_waT[(cc + 2) * CCH + c0];
        float4 w3 = *(const float4*)&g_waT[(cc + 3) * CCH + c0];
        #pragma unroll
        for (int i = 0; i < 4; i++) {
            float4 a = *(const float4*)&avs[(n0 + i) * CCH + cc];
            acc[i][0] += a.x * w0.x + a.y * w1.x + a.z * w2.x + a.w * w3.x;
            acc[i][1] += a.x * w0.y + a.y * w1.y + a.z * w2.y + a.w * w3.y;
            acc[i][2] += a.x * w0.z + a.y * w1.z + a.z * w2.z + a.w * w3.z;
            acc[i][3] += a.x * w0.w + a.y * w1.w + a.z * w2.w + a.w * w3.w;
        }
    }
    #pragma unroll
    for (int k = 0; k < 4; k++) {
        float b = ba[c0 + k];
        float cs = 0.f, cq2 = 0.f;
        #pragma unroll
        for (int i = 0; i < 4; i++) {
            float yv = acc[i][k] + b;
            g_y[(size_t)(c0 + k) * NPOS + nbase + n0 + i] = yv;
            cs += yv; cq2 += yv * yv;
        }
        atomicAdd(&ssum[c0 + k], cs);
        atomicAdd(&ssq[c0 + k], cq2);
    }
    __syncthreads();
    if (tid < CCH) {
        atomicAdd(&g_sum[tid], ssum[tid]);
        atomicAdd(&g_sq[tid],  ssq[tid]);
    }
}

// ---------------- kernel: BN (from global sums) + ReLU + residual, float4 ----------------
__global__ void k_final(const float* __restrict__ x,
                        const float* __restrict__ bnw, const float* __restrict__ bnb,
                        float* __restrict__ out) {
    const int i4 = (blockIdx.x * 256 + threadIdx.x) * 4;   // NPOS*CCH/4 threads
    const int c = i4 / NPOS;                                // 8000 % 4 == 0 -> no straddle
    const float inv = 1.f / (float)NPOS;
    float mean = g_sum[c] * inv;
    float var = g_sq[c] * inv - mean * mean;
    float rstd = rsqrtf(var + 1e-5f);
    float s = rstd * bnw[c];
    float bb = bnb[c] - mean * s;
    float4 yv = *(const float4*)&g_y[i4];
    float4 xv = *(const float4*)&x[i4];
    float4 o;
    o.x = fmaxf(yv.x * s + bb, 0.f) + xv.x;
    o.y = fmaxf(yv.y * s + bb, 0.f) + xv.y;
    o.z = fmaxf(yv.z * s + bb, 0.f) + xv.z;
    o.w = fmaxf(yv.w * s + bb, 0.f) + xv.w;
    *(float4*)&out[i4] = o;
}

// ---------------- launch ----------------
extern "C" void kernel_launch(void* const* d_in, const int* in_sizes, int n_in,
                              void* d_out, int out_size) {
    const float* x   = (const float*)d_in[0];
    const float* wq  = (const float*)d_in[1];
    const float* bq  = (const float*)d_in[2];
    const float* wk  = (const float*)d_in[3];
    const float* bk  = (const float*)d_in[4];
    const float* wv  = (const float*)d_in[5];
    const float* bv  = (const float*)d_in[6];
    const float* wa  = (const float*)d_in[7];
    const float* ba  = (const float*)d_in[8];
    const float* bnw = (const float*)d_in[9];
    const float* bnb = (const float*)d_in[10];
    float* out = (float*)d_out;

    static int smem_set = 0;
    if (!smem_set) {
        cudaFuncSetAttribute(k_flash_mma, cudaFuncAttributeMaxDynamicSharedMemorySize,
                             FLASH_SMEM);
        smem_set = 1;
    }

    k_pre<<<814, 256>>>(x, wq, bq, wk, bk, wv, bv, wa);
    k_flash_mma<<<dim3(QT, NSPLIT), 256, FLASH_SMEM>>>();
    k_ygemm<<<NPOS / 32, 256>>>(ba);
    k_final<<<(NPOS * CCH / 4) / 256, 256>>>(x, bnw, bnb, out);
}